// round 13
// baseline (speedup 1.0000x reference)
#include <cuda_runtime.h>
#include <cuda_bf16.h>

// GaussianModel: cov = (R*diag(s)) (R*diag(s))^T per Gaussian, N=4M.
// Inputs: rotation_raw float32 [N,4], scaling_raw float32 [N,3]
// Output: cov float32 [N,3,3]
//
// R12: persistent grid-stride + distance-1 tile prefetch. R11 proved per-warp
// MLP (not occupancy) is the lever; this removes the remaining exposed
// latency: per-block cold start on every one of 3907 blocks. Now 592
// persistent blocks; while computing tile t, quats (regs) and scales
// (double-buffered smem) for tile t+P are in flight. Access patterns
// unchanged from R11 (all contiguous float4, warp-autonomous, __syncwarp).

__device__ __forceinline__ void cov_one(float4 q, float a0, float a1, float a2,
                                        float* __restrict__ o /* 9 floats */)
{
    float w = q.x, x = q.y, y = q.z, z = q.w;

    // R is quadratic in the normalized quaternion: fold 2/||q||^2 into the
    // cross terms instead of normalizing.
    float n2   = w*w + x*x + y*y + z*z;
    float inv2 = __fdividef(2.0f, n2);

    float xx = x*x*inv2, yy = y*y*inv2, zz = z*z*inv2;
    float xy = x*y*inv2, xz = x*z*inv2, yz = y*z*inv2;
    float wx = w*x*inv2, wy = w*y*inv2, wz = w*z*inv2;

    float r00 = 1.0f - yy - zz, r01 = xy - wz,        r02 = xz + wy;
    float r10 = xy + wz,        r11 = 1.0f - xx - zz, r12 = yz - wx;
    float r20 = xz - wy,        r21 = yz + wx,        r22 = 1.0f - xx - yy;

    // s_k^2 = exp(2 * raw_k)
    float s00 = __expf(2.0f * a0);
    float s11 = __expf(2.0f * a1);
    float s22 = __expf(2.0f * a2);

    float c00 = r00*r00*s00 + r01*r01*s11 + r02*r02*s22;
    float c01 = r00*r10*s00 + r01*r11*s11 + r02*r12*s22;
    float c02 = r00*r20*s00 + r01*r21*s11 + r02*r22*s22;
    float c11 = r10*r10*s00 + r11*r11*s11 + r12*r12*s22;
    float c12 = r10*r20*s00 + r11*r21*s11 + r12*r22*s22;
    float c22 = r20*r20*s00 + r21*r21*s11 + r22*r22*s22;

    // STS.32 stride-9: gcd(9,32)=1 -> conflict-free
    o[0] = c00; o[1] = c01; o[2] = c02;
    o[3] = c01; o[4] = c11; o[5] = c12;
    o[6] = c02; o[7] = c12; o[8] = c22;
}

__global__ __launch_bounds__(256, 4)
void gaussian_cov_kernel(const float4* __restrict__ rot,
                         const float*  __restrict__ sc,
                         float*        __restrict__ out,
                         int n, int nTiles)
{
    // Per-warp: double-buffered 384-float scale slices + 576-float out buffer
    // (reused across two 64-elem phases). 8 warps: 24 KB + 18 KB = 42 KB.
    __shared__ float sh_s[8][2][384];
    __shared__ float sh_o[8][576];

    const int tid  = threadIdx.x;
    const int wrp  = tid >> 5;
    const int lane = tid & 31;

    int  t    = blockIdx.x;                    // logical 1024-elem tile
    bool full = (t * 1024 + 1024 <= n);
    int  buf  = 0;

    // ---- Preload tile t (warp-private) ----
    float4 q0 = make_float4(0,0,0,0), q1 = q0, q2 = q0, q3 = q0;
    if (full) {
        const int eb = t * 1024 + 128 * wrp;
        q0 = __ldcs(&rot[eb + lane]);
        q1 = __ldcs(&rot[eb + 32 + lane]);
        q2 = __ldcs(&rot[eb + 64 + lane]);
        q3 = __ldcs(&rot[eb + 96 + lane]);
        const float4* s4 = (const float4*)(sc + 3 * eb);
        float4* sh4 = (float4*)sh_s[wrp][0];
        sh4[lane]      = __ldcs(&s4[lane]);
        sh4[lane + 32] = __ldcs(&s4[lane + 32]);
        sh4[lane + 64] = __ldcs(&s4[lane + 64]);
    }

    for (;;) {
        const int  tn    = t + gridDim.x;
        const bool fulln = (tn * 1024 + 1024 <= n);   // implies tn < nTiles

        if (full) {
            const int eb = t * 1024 + 128 * wrp;

            // ---- Issue next tile's loads (distance-1 prefetch) ----
            float4 qn0 = q0, qn1 = q1, qn2 = q2, qn3 = q3;
            float4 sn0, sn1, sn2;
            if (fulln) {
                const int ebn = tn * 1024 + 128 * wrp;
                qn0 = __ldcs(&rot[ebn + lane]);
                qn1 = __ldcs(&rot[ebn + 32 + lane]);
                qn2 = __ldcs(&rot[ebn + 64 + lane]);
                qn3 = __ldcs(&rot[ebn + 96 + lane]);
                const float4* s4n = (const float4*)(sc + 3 * ebn);
                sn0 = __ldcs(&s4n[lane]);
                sn1 = __ldcs(&s4n[lane + 32]);
                sn2 = __ldcs(&s4n[lane + 64]);
            }
            __syncwarp();   // staged scales (prev iter / preload) visible

            const float*  ss  = sh_s[wrp][buf];
            float*        so  = sh_o[wrp];
            float4*       dst = (float4*)(out + 9 * eb);   // 288 float4
            const float4* src = (const float4*)so;

            // ---- Phase A: elems [0,64) -> store float4 [0,144) ----
            {
                int l = lane;
                cov_one(q0, ss[3*l], ss[3*l+1], ss[3*l+2], so + 9*l);
                l = lane + 32;
                cov_one(q1, ss[3*l], ss[3*l+1], ss[3*l+2], so + 9*l);
            }
            __syncwarp();
            __stcs(&dst[lane],       src[lane]);
            __stcs(&dst[lane +  32], src[lane +  32]);
            __stcs(&dst[lane +  64], src[lane +  64]);
            __stcs(&dst[lane +  96], src[lane +  96]);
            if (lane < 16)
                __stcs(&dst[lane + 128], src[lane + 128]);

            // ---- Stash next-tile scales (LDG latency now covered) ----
            if (fulln) {
                float4* sh4 = (float4*)sh_s[wrp][buf ^ 1];
                sh4[lane]      = sn0;
                sh4[lane + 32] = sn1;
                sh4[lane + 64] = sn2;
            }

            // ---- Phase B: elems [64,128) -> store float4 [144,288) ----
            {
                int l = lane;
                cov_one(q2, ss[3*(64+l)], ss[3*(64+l)+1], ss[3*(64+l)+2],
                        so + 9*l);
                cov_one(q3, ss[3*(96+l)], ss[3*(96+l)+1], ss[3*(96+l)+2],
                        so + 9*(l + 32));
            }
            __syncwarp();   // also orders the STS above before next-iter reads
            __stcs(&dst[lane + 144], src[lane]);
            __stcs(&dst[lane + 176], src[lane +  32]);
            __stcs(&dst[lane + 208], src[lane +  64]);
            __stcs(&dst[lane + 240], src[lane +  96]);
            if (lane < 16)
                __stcs(&dst[lane + 272], src[lane + 128]);

            q0 = qn0; q1 = qn1; q2 = qn2; q3 = qn3;
        } else {
            // ---- guarded tail path (single partial tile) ----
            const int base = t * 1024;
            #pragma unroll
            for (int e = 0; e < 4; e++) {
                int i = base + tid + 256 * e;
                if (i < n) {
                    float4 q = __ldg(&rot[i]);
                    float c[9];
                    cov_one(q, __ldg(sc + 3*i), __ldg(sc + 3*i + 1),
                            __ldg(sc + 3*i + 2), c);
                    float* o = out + 9 * i;
                    #pragma unroll
                    for (int k = 0; k < 9; k++) o[k] = c[k];
                }
            }
        }

        t = tn;
        buf ^= 1;
        if (t >= nTiles) break;
        full = (t * 1024 + 1024 <= n);
    }
}

extern "C" void kernel_launch(void* const* d_in, const int* in_sizes, int n_in,
                              void* d_out, int out_size)
{
    const float4* rot = (const float4*)d_in[0];   // [N,4] float32
    const float*  sc  = (const float*) d_in[1];   // [N,3] float32
    float*        out = (float*)d_out;            // [N,3,3] float32

    int n      = in_sizes[0] / 4;
    int nTiles = (n + 1023) / 1024;
    int P      = 148 * 4;                         // persistent blocks
    if (P > nTiles) P = nTiles;
    gaussian_cov_kernel<<<P, 256>>>(rot, sc, out, n, nTiles);
}

// round 14
// speedup vs baseline: 1.0624x; 1.0624x over previous
#include <cuda_runtime.h>
#include <cuda_bf16.h>

// GaussianModel: cov = (R*diag(s)) (R*diag(s))^T per Gaussian, N=4M.
// Inputs: rotation_raw float32 [N,4], scaling_raw float32 [N,3]
// Output: cov float32 [N,3,3]
//
// R13: revert R12's persistent loop (regs 64, occ 38%, regression). Back to
// R11's proven flat-grid warp-autonomous shape, warp tile widened 128->192
// elems (6/thread): ~10.5 front-batched LDG.128/lane, three compute->store
// phases reusing one 576-float out buffer. smem ~37KB, all global traffic
// contiguous float4, __syncwarp only.

__device__ __forceinline__ void cov_one(float4 q, float a0, float a1, float a2,
                                        float* __restrict__ o /* 9 floats */)
{
    float w = q.x, x = q.y, y = q.z, z = q.w;

    // R is quadratic in the normalized quaternion: fold 2/||q||^2 into the
    // cross terms instead of normalizing.
    float n2   = w*w + x*x + y*y + z*z;
    float inv2 = __fdividef(2.0f, n2);

    float xx = x*x*inv2, yy = y*y*inv2, zz = z*z*inv2;
    float xy = x*y*inv2, xz = x*z*inv2, yz = y*z*inv2;
    float wx = w*x*inv2, wy = w*y*inv2, wz = w*z*inv2;

    float r00 = 1.0f - yy - zz, r01 = xy - wz,        r02 = xz + wy;
    float r10 = xy + wz,        r11 = 1.0f - xx - zz, r12 = yz - wx;
    float r20 = xz - wy,        r21 = yz + wx,        r22 = 1.0f - xx - yy;

    // s_k^2 = exp(2 * raw_k)
    float s00 = __expf(2.0f * a0);
    float s11 = __expf(2.0f * a1);
    float s22 = __expf(2.0f * a2);

    float c00 = r00*r00*s00 + r01*r01*s11 + r02*r02*s22;
    float c01 = r00*r10*s00 + r01*r11*s11 + r02*r12*s22;
    float c02 = r00*r20*s00 + r01*r21*s11 + r02*r22*s22;
    float c11 = r10*r10*s00 + r11*r11*s11 + r12*r12*s22;
    float c12 = r10*r20*s00 + r11*r21*s11 + r12*r22*s22;
    float c22 = r20*r20*s00 + r21*r21*s11 + r22*r22*s22;

    // STS.32 stride-9: gcd(9,32)=1 -> conflict-free
    o[0] = c00; o[1] = c01; o[2] = c02;
    o[3] = c01; o[4] = c11; o[5] = c12;
    o[6] = c02; o[7] = c12; o[8] = c22;
}

__global__ __launch_bounds__(256)
void gaussian_cov_kernel(const float4* __restrict__ rot,
                         const float*  __restrict__ sc,
                         float*        __restrict__ out,
                         int n)
{
    // Per-warp: 576 scale floats (192 elems) + 576-float out buffer reused
    // across three 64-elem phases. 8 warps: 18.4 KB + 18.4 KB ~= 37 KB.
    __shared__ float sh_s[8][576];
    __shared__ float sh_o[8][576];

    const int tid  = threadIdx.x;
    const int wrp  = tid >> 5;
    const int lane = tid & 31;
    const int base = blockIdx.x * 1536;

    if (base + 1536 <= n) {
        // ============ guardless warp-autonomous fast path ============
        const int eb = base + 192 * wrp;       // this warp's 192 elements

        // ---- Front-batch ~10.5 LDG.128 per lane (max MLP) ----
        float4 q0 = __ldcs(&rot[eb + lane]);
        float4 q1 = __ldcs(&rot[eb +  32 + lane]);
        float4 q2 = __ldcs(&rot[eb +  64 + lane]);
        float4 q3 = __ldcs(&rot[eb +  96 + lane]);
        float4 q4 = __ldcs(&rot[eb + 128 + lane]);
        float4 q5 = __ldcs(&rot[eb + 160 + lane]);

        {   // 576 scale floats = 144 float4 at sc + 3*eb (3*eb % 4 == 0)
            const float4* s4 = (const float4*)(sc + 3 * eb);
            float4* sh4 = (float4*)sh_s[wrp];
            sh4[lane]      = __ldcs(&s4[lane]);
            sh4[lane + 32] = __ldcs(&s4[lane + 32]);
            sh4[lane + 64] = __ldcs(&s4[lane + 64]);
            sh4[lane + 96] = __ldcs(&s4[lane + 96]);
            if (lane < 16)
                sh4[lane + 128] = __ldcs(&s4[lane + 128]);
        }
        __syncwarp();

        const float*  ss  = sh_s[wrp];
        float*        so  = sh_o[wrp];
        float4*       dst = (float4*)(out + 9 * eb);   // 432 float4 total
        const float4* src = (const float4*)so;

        // ---- Phase A: elems [0,64) -> store float4 [0,144) ----
        cov_one(q0, ss[3*lane],      ss[3*lane+1],      ss[3*lane+2],
                so + 9*lane);
        cov_one(q1, ss[3*(32+lane)], ss[3*(32+lane)+1], ss[3*(32+lane)+2],
                so + 9*(lane+32));
        __syncwarp();
        __stcs(&dst[lane],       src[lane]);
        __stcs(&dst[lane +  32], src[lane +  32]);
        __stcs(&dst[lane +  64], src[lane +  64]);
        __stcs(&dst[lane +  96], src[lane +  96]);
        if (lane < 16)
            __stcs(&dst[lane + 128], src[lane + 128]);
        // In-warp program order: phase-A LDS precede phase-B STS; reuse safe.

        // ---- Phase B: elems [64,128) -> store float4 [144,288) ----
        cov_one(q2, ss[3*(64+lane)], ss[3*(64+lane)+1], ss[3*(64+lane)+2],
                so + 9*lane);
        cov_one(q3, ss[3*(96+lane)], ss[3*(96+lane)+1], ss[3*(96+lane)+2],
                so + 9*(lane+32));
        __syncwarp();
        __stcs(&dst[lane + 144], src[lane]);
        __stcs(&dst[lane + 176], src[lane +  32]);
        __stcs(&dst[lane + 208], src[lane +  64]);
        __stcs(&dst[lane + 240], src[lane +  96]);
        if (lane < 16)
            __stcs(&dst[lane + 272], src[lane + 128]);

        // ---- Phase C: elems [128,192) -> store float4 [288,432) ----
        cov_one(q4, ss[3*(128+lane)], ss[3*(128+lane)+1], ss[3*(128+lane)+2],
                so + 9*lane);
        cov_one(q5, ss[3*(160+lane)], ss[3*(160+lane)+1], ss[3*(160+lane)+2],
                so + 9*(lane+32));
        __syncwarp();
        __stcs(&dst[lane + 288], src[lane]);
        __stcs(&dst[lane + 320], src[lane +  32]);
        __stcs(&dst[lane + 352], src[lane +  64]);
        __stcs(&dst[lane + 384], src[lane +  96]);
        if (lane < 16)
            __stcs(&dst[lane + 416], src[lane + 128]);
    } else {
        // ============ guarded tail path (last partial block) =========
        #pragma unroll
        for (int e = 0; e < 6; e++) {
            int i = base + tid + 256 * e;
            if (i < n) {
                float4 q = __ldg(&rot[i]);
                float c[9];
                cov_one(q, __ldg(sc + 3*i), __ldg(sc + 3*i + 1),
                        __ldg(sc + 3*i + 2), c);
                float* o = out + 9 * i;
                #pragma unroll
                for (int k = 0; k < 9; k++) o[k] = c[k];
            }
        }
    }
}

extern "C" void kernel_launch(void* const* d_in, const int* in_sizes, int n_in,
                              void* d_out, int out_size)
{
    const float4* rot = (const float4*)d_in[0];   // [N,4] float32
    const float*  sc  = (const float*) d_in[1];   // [N,3] float32
    float*        out = (float*)d_out;            // [N,3,3] float32

    int n  = in_sizes[0] / 4;
    int nb = (n + 1535) / 1536;
    gaussian_cov_kernel<<<nb, 256>>>(rot, sc, out, n);
}